// round 6
// baseline (speedup 1.0000x reference)
#include <cuda_runtime.h>
#include <math.h>

#define VOL   128
#define VOL2  (VOL*VOL)
#define VOL3  (VOL*VOL*VOL)
#define NB    4
#define NVOX  (NB*VOL3)
#define OTY   26              // output rows per block tile (y)
#define NTY   5               // ceil(128/26)
#define ZSEG  7               // z segments per volume (140 blocks = 1 wave)
#define ZLEN  19

#define PINF __int_as_float(0x7f800000)
#define NINF __int_as_float(0xff800000)

__device__ float g_yp[NVOX];
__device__ float g_imgA[NVOX];
__device__ float g_imgB[NVOX];
__device__ float g_skel[NVOX];
__device__ float g_acc[8];

__device__ __forceinline__ const float* pick(int sel, const float* ext) {
    if (sel == 0) return g_imgA;
    if (sel == 1) return g_imgB;
    if (sel == 2) return g_yp;
    return ext;
}

__device__ __forceinline__ float4 f4(float v) { return make_float4(v, v, v, v); }
__device__ __forceinline__ float4 vmin(float4 a, float4 b) {
    return make_float4(fminf(a.x,b.x), fminf(a.y,b.y), fminf(a.z,b.z), fminf(a.w,b.w));
}
__device__ __forceinline__ float4 vmax(float4 a, float4 b) {
    return make_float4(fmaxf(a.x,b.x), fmaxf(a.y,b.y), fmaxf(a.z,b.z), fmaxf(a.w,b.w));
}
__device__ __forceinline__ float4 vmin3(float4 a, float4 b, float4 c) { return vmin(vmin(a,b),c); }
__device__ __forceinline__ float4 vmax3(float4 a, float4 b, float4 c) { return vmax(vmax(a,b),c); }

__device__ __forceinline__ float4 hmin_shfl(float4 a, int tx) {
    float aL = __shfl_up_sync(0xffffffffu, a.w, 1);
    float aR = __shfl_down_sync(0xffffffffu, a.x, 1);
    if (tx == 0)  aL = a.x;
    if (tx == 31) aR = a.w;
    float m01 = fminf(a.x, a.y), m12 = fminf(a.y, a.z), m23 = fminf(a.z, a.w);
    return make_float4(fminf(aL, m01), fminf(m01, a.z), fminf(m12, a.w), fminf(m23, aR));
}
__device__ __forceinline__ float4 hmax_shfl(float4 a, int tx) {
    float aL = __shfl_up_sync(0xffffffffu, a.w, 1);
    float aR = __shfl_down_sync(0xffffffffu, a.x, 1);
    if (tx == 0)  aL = a.x;
    if (tx == 31) aR = a.w;
    float m01 = fmaxf(a.x, a.y), m12 = fmaxf(a.y, a.z), m23 = fmaxf(a.z, a.w);
    return make_float4(fmaxf(aL, m01), fmaxf(m01, a.z), fmaxf(m12, a.w), fmaxf(m23, aR));
}

__global__ void zero_acc_kernel() {
    if (threadIdx.x < 8) g_acc[threadIdx.x] = 0.f;
}

// ---------------------------------------------------------------------------
// prep
// ---------------------------------------------------------------------------
__global__ __launch_bounds__(256) void prep_kernel(const float* __restrict__ pred,
                                                   const float* __restrict__ tru) {
    __shared__ float sm[3][8];
    const float4* p4 = (const float4*)pred;
    const float4* t4 = (const float4*)tru;
    float4* y4 = (float4*)g_yp;
    int base = blockIdx.x * 1024 + threadIdx.x;
    float st = 0.f, sp = 0.f, stp = 0.f;
#pragma unroll
    for (int k = 0; k < 4; k++) {
        int i = base + k * 256;
        float4 t = t4[i];
        float4 x = p4[i];
        float4 p;
        p.x = 1.f / (1.f + __expf(-x.x));
        p.y = 1.f / (1.f + __expf(-x.y));
        p.z = 1.f / (1.f + __expf(-x.z));
        p.w = 1.f / (1.f + __expf(-x.w));
        y4[i] = p;
        st  += (t.x + t.y) + (t.z + t.w);
        sp  += (p.x + p.y) + (p.z + p.w);
        stp += (t.x*p.x + t.y*p.y) + (t.z*p.z + t.w*p.w);
    }
#pragma unroll
    for (int o = 16; o > 0; o >>= 1) {
        st  += __shfl_xor_sync(0xffffffffu, st,  o);
        sp  += __shfl_xor_sync(0xffffffffu, sp,  o);
        stp += __shfl_xor_sync(0xffffffffu, stp, o);
    }
    int w = threadIdx.x >> 5, lane = threadIdx.x & 31;
    if (lane == 0) { sm[0][w] = st; sm[1][w] = sp; sm[2][w] = stp; }
    __syncthreads();
    if (threadIdx.x == 0) {
        float a = 0.f, b = 0.f, c = 0.f;
#pragma unroll
        for (int i = 0; i < 8; i++) { a += sm[0][i]; b += sm[1][i]; c += sm[2][i]; }
        atomicAdd(&g_acc[0], a); atomicAdd(&g_acc[1], b); atomicAdd(&g_acc[2], c);
    }
}

// ---------------------------------------------------------------------------
// init: skel = relu(x - dilate(erode(x)))  (2 syncs/plane)
// ---------------------------------------------------------------------------
__global__ __launch_bounds__(1024) void init_kernel(int inSel, const float* __restrict__ extIn) {
    __shared__ float4 As[32][32];
    __shared__ float4 Ms[32][32];
    const float* __restrict__ x = pick(inSel, extIn);

    const int tx = threadIdx.x, ty = threadIdx.y;
    const int b   = blockIdx.z;
    const int oz0 = blockIdx.y * ZLEN;
    const int oz1 = min(oz0 + ZLEN, VOL);
    const int gy  = blockIdx.x * OTY - 3 + ty;
    const bool vrow = (gy >= 0 && gy < VOL);
    const bool wr   = vrow && ty >= 3 && ty < 29;
    const int ym = ty > 0 ? ty - 1 : 0, yp = ty < 31 ? ty + 1 : 31;
    const int bOff = b * VOL3;
    const int rowOff = bOff + (vrow ? gy : 0) * VOL + tx * 4;

    float4 a_m1 = f4(PINF), a_m2 = f4(PINF), bxy_m1 = f4(PINF);
    float4 m_m1 = f4(NINF), m_m2 = f4(NINF);

    int z0 = oz0 - 2;
    float4 cur = f4(PINF);
    if (vrow && (unsigned)z0 < (unsigned)VOL)
        cur = *(const float4*)(x + z0 * VOL2 + rowOff);
    As[ty][tx] = cur;
    __syncthreads();

    for (int z = z0; z <= oz1 + 1; ++z) {
        float4 nxt = f4(PINF);
        if (vrow && (unsigned)(z + 1) < (unsigned)VOL)
            nxt = *(const float4*)(x + (z + 1) * VOL2 + rowOff);

        float4 up = As[ym][tx], dn = As[yp][tx];
        float4 h  = hmin_shfl(cur, tx);
        float4 bxy = vmin3(h, up, dn);
        float4 e1 = vmin3(a_m2, cur, bxy_m1);
        if (!vrow || (unsigned)(z - 1) >= (unsigned)VOL) e1 = f4(NINF);
        float4 hm = hmax_shfl(e1, tx);
        Ms[ty][tx] = hm;
        __syncthreads();
        As[ty][tx] = nxt;
        float4 mxy = vmax3(hm, Ms[ym][tx], Ms[yp][tx]);
        int zo = z - 2;
        if (wr && zo >= oz0 && zo < oz1) {
            float4 openv = vmax3(m_m2, m_m1, mxy);
            float4 s;
            s.x = fmaxf(a_m2.x - openv.x, 0.f);
            s.y = fmaxf(a_m2.y - openv.y, 0.f);
            s.z = fmaxf(a_m2.z - openv.z, 0.f);
            s.w = fmaxf(a_m2.w - openv.w, 0.f);
            *(float4*)(g_skel + zo * VOL2 + rowOff) = s;
        }
        __syncthreads();
        a_m2 = a_m1; a_m1 = cur; bxy_m1 = bxy;
        m_m2 = m_m1; m_m1 = mxy;
        cur = nxt;
    }
}

// ---------------------------------------------------------------------------
// iter: skewed pipeline, ONE barrier per plane, double-buffered As/Es/Ms.
// ---------------------------------------------------------------------------
__global__ __launch_bounds__(1024) void iter_kernel(
    int inSel, const float* __restrict__ extIn, int outSel,
    int doSum, int otherSel, const float* __restrict__ extOther, int accBase)
{
    extern __shared__ float4 smem[];   // 6 buffers of 32*32 float4 (96 KB)
    float4* AsB[2] = { smem,          smem + 1024 };
    float4* EsB[2] = { smem + 2048,   smem + 3072 };
    float4* MsB[2] = { smem + 4096,   smem + 5120 };

    const float* __restrict__ imgIn = pick(inSel, extIn);
    float* imgOut = (outSel == 0) ? g_imgA : g_imgB;
    const float* __restrict__ other = pick(otherSel, extOther);

    const int tx = threadIdx.x, ty = threadIdx.y;
    const int b   = blockIdx.z;
    const int oz0 = blockIdx.y * ZLEN;
    const int oz1 = min(oz0 + ZLEN, VOL);
    const int gy  = blockIdx.x * OTY - 3 + ty;
    const bool vrow = (gy >= 0 && gy < VOL);
    const bool wr   = vrow && ty >= 3 && ty < 29;
    const int ym = ty > 0 ? ty - 1 : 0, yp = ty < 31 ? ty + 1 : 31;
    const int bOff = b * VOL3;
    const int rowOff = bOff + (vrow ? gy : 0) * VOL + tx * 4;
    const int sIdx = ty * 32 + tx;

    float4 a_m1 = f4(PINF), a_m2 = f4(PINF), bxy_m1 = f4(PINF);
    float4 E1 = f4(PINF), E2 = f4(PINF), E3 = f4(PINF);
    float4 hm_m1 = f4(NINF), m_m1 = f4(NINF), m_m2 = f4(NINF);
    float sumS = 0.f, sumC = 0.f;

    int z0 = oz0 - 3;
    float4 cur = f4(PINF);
    if (vrow && (unsigned)z0 < (unsigned)VOL)
        cur = *(const float4*)(imgIn + z0 * VOL2 + rowOff);
    AsB[0][sIdx] = cur;
    EsB[0][sIdx] = f4(PINF);
    MsB[0][sIdx] = f4(NINF);
    __syncthreads();

    int rb = 0;
    for (int z = z0; z <= oz1 + 3; ++z) {
        const float4* AsR = AsB[rb];
        const float4* EsR = EsB[rb];
        const float4* MsR = MsB[rb];
        float4* AsW = AsB[rb ^ 1];
        float4* EsW = EsB[rb ^ 1];
        float4* MsW = MsB[rb ^ 1];

        float4 nxt = f4(PINF);
        if (vrow && (unsigned)(z + 1) < (unsigned)VOL)
            nxt = *(const float4*)(imgIn + (z + 1) * VOL2 + rowOff);

        // stage 1: bxy(z), e1(z-1)
        float4 up = AsR[ym * 32 + tx], dn = AsR[yp * 32 + tx];
        float4 h  = hmin_shfl(cur, tx);
        float4 bxy = vmin3(h, up, dn);
        float4 e1 = vmin3(a_m2, cur, bxy_m1);
        if (!vrow || (unsigned)(z - 1) >= (unsigned)VOL) e1 = f4(PINF);

        // stage 2: cxy(z-2), e2(z-2)
        float4 upe = EsR[ym * 32 + tx], dne = EsR[yp * 32 + tx];
        float4 h2  = hmin_shfl(E1, tx);
        float4 cxy = vmin3(h2, upe, dne);
        float4 e2 = vmin3(E2, e1, cxy);
        if (!vrow || (unsigned)(z - 2) >= (unsigned)VOL) e2 = f4(NINF);
        float4 hm = hmax_shfl(e2, tx);

        // stage 3: mxy(z-3)
        float4 mxy = vmax3(hm_m1, MsR[ym * 32 + tx], MsR[yp * 32 + tx]);

        // output zo = z-4
        int zo = z - 4;
        if (wr && zo >= oz0 && zo < oz1) {
            float4 openv = vmax3(m_m2, m_m1, mxy);
            float4 imgN = E3;
            float4 delta;
            delta.x = fmaxf(imgN.x - openv.x, 0.f);
            delta.y = fmaxf(imgN.y - openv.y, 0.f);
            delta.z = fmaxf(imgN.z - openv.z, 0.f);
            delta.w = fmaxf(imgN.w - openv.w, 0.f);
            int gi = zo * VOL2 + rowOff;
            float4 s = *(float4*)(g_skel + gi);
            s.x += fmaxf(fmaf(-s.x, delta.x, delta.x), 0.f);
            s.y += fmaxf(fmaf(-s.y, delta.y, delta.y), 0.f);
            s.z += fmaxf(fmaf(-s.z, delta.z, delta.z), 0.f);
            s.w += fmaxf(fmaf(-s.w, delta.w, delta.w), 0.f);
            *(float4*)(g_skel + gi) = s;
            *(float4*)(imgOut + gi) = imgN;
            if (doSum) {
                float4 o = *(const float4*)(other + gi);
                sumS += (s.x + s.y) + (s.z + s.w);
                sumC += (s.x*o.x + s.y*o.y) + (s.z*o.z + s.w*o.w);
            }
        }

        // writes for next iteration
        AsW[sIdx] = nxt;
        EsW[sIdx] = e1;
        MsW[sIdx] = hm;
        __syncthreads();

        // shift histories
        a_m2 = a_m1; a_m1 = cur; cur = nxt; bxy_m1 = bxy;
        E3 = E2; E2 = E1; E1 = e1;
        hm_m1 = hm; m_m2 = m_m1; m_m1 = mxy;
        rb ^= 1;
    }

    if (doSum) {
#pragma unroll
        for (int o = 16; o > 0; o >>= 1) {
            sumS += __shfl_xor_sync(0xffffffffu, sumS, o);
            sumC += __shfl_xor_sync(0xffffffffu, sumC, o);
        }
        int w = sIdx >> 5, lane = sIdx & 31;
        float* red = (float*)smem;
        if (lane == 0) { red[w] = sumS; red[32 + w] = sumC; }
        __syncthreads();
        if (w == 0) {
            float s = red[lane], c = red[32 + lane];
#pragma unroll
            for (int o = 16; o > 0; o >>= 1) {
                s += __shfl_xor_sync(0xffffffffu, s, o);
                c += __shfl_xor_sync(0xffffffffu, c, o);
            }
            if (lane == 0) {
                atomicAdd(&g_acc[accBase], s);
                atomicAdd(&g_acc[accBase + 1], c);
            }
        }
    }
}

__global__ void final_kernel(float* out) {
    float st = g_acc[0], sp = g_acc[1], stp = g_acc[2];
    float skp = g_acc[3], skpt = g_acc[4], skt = g_acc[5], sktp = g_acc[6];
    float dice = 1.f - (2.f * stp + 1.f) / (st + sp + 1.f);
    float tprec = (skpt + 1.f) / (skp + 1.f);
    float tsens = (sktp + 1.f) / (skt + 1.f);
    float cl = 1.f - 2.f * (tprec * tsens) / (tprec + tsens);
    out[0] = 0.7f * dice + 0.3f * cl;
}

#define ITER_SMEM (6 * 1024 * 16)   // 96 KB

extern "C" void kernel_launch(void* const* d_in, const int* in_sizes, int n_in,
                              void* d_out, int out_size) {
    const float* pred = (const float*)d_in[0];
    const float* tru  = (const float*)d_in[1];
    float* out = (float*)d_out;

    static int smem_set = 0;
    if (!smem_set) {
        cudaFuncSetAttribute(iter_kernel, cudaFuncAttributeMaxDynamicSharedMemorySize, ITER_SMEM);
        smem_set = 1;
    }

    dim3 blk(32, 32);
    dim3 grd(NTY, ZSEG, NB);

    zero_acc_kernel<<<1, 32>>>();
    prep_kernel<<<NVOX / 4096, 256>>>(pred, tru);

    // ---- pred skeleton ----
    init_kernel<<<grd, blk>>>(2, nullptr);
    iter_kernel<<<grd, blk, ITER_SMEM>>>(2, nullptr, 0, 0, 0, nullptr, 0);
    for (int k = 2; k <= 16; ++k) {
        int inSel  = (k & 1) ? 1 : 0;
        int outSel = (k & 1) ? 0 : 1;
        int doSum  = (k == 16) ? 1 : 0;
        iter_kernel<<<grd, blk, ITER_SMEM>>>(inSel, nullptr, outSel, doSum, 3, tru, 3);
    }

    // ---- true skeleton ----
    init_kernel<<<grd, blk>>>(3, tru);
    iter_kernel<<<grd, blk, ITER_SMEM>>>(3, tru, 0, 0, 0, nullptr, 0);
    for (int k = 2; k <= 16; ++k) {
        int inSel  = (k & 1) ? 1 : 0;
        int outSel = (k & 1) ? 0 : 1;
        int doSum  = (k == 16) ? 1 : 0;
        iter_kernel<<<grd, blk, ITER_SMEM>>>(inSel, nullptr, outSel, doSum, 2, nullptr, 5);
    }

    final_kernel<<<1, 1>>>(out);
}

// round 7
// speedup vs baseline: 2.1779x; 2.1779x over previous
#include <cuda_runtime.h>
#include <math.h>

#define VOL   128
#define VOL2  (VOL*VOL)
#define VOL3  (VOL*VOL*VOL)
#define NB    4
#define NVOX  (NB*VOL3)
#define OTY   26              // output rows per block tile (y)
#define NTY   5               // ceil(128/26)
#define ZSEG  7               // 140 blocks = 1 wave
#define ZLEN  19

#define PINF __int_as_float(0x7f800000)
#define NINF __int_as_float(0xff800000)

__device__ float g_yp[NVOX];
__device__ float g_imgA[NVOX];
__device__ float g_imgB[NVOX];
__device__ float g_skel[NVOX];
__device__ float g_acc[8];

__device__ __forceinline__ const float* pick(int sel, const float* ext) {
    if (sel == 0) return g_imgA;
    if (sel == 1) return g_imgB;
    if (sel == 2) return g_yp;
    return ext;
}

__device__ __forceinline__ float4 f4(float v) { return make_float4(v, v, v, v); }
__device__ __forceinline__ float4 vmin(float4 a, float4 b) {
    return make_float4(fminf(a.x,b.x), fminf(a.y,b.y), fminf(a.z,b.z), fminf(a.w,b.w));
}
__device__ __forceinline__ float4 vmax(float4 a, float4 b) {
    return make_float4(fmaxf(a.x,b.x), fmaxf(a.y,b.y), fmaxf(a.z,b.z), fmaxf(a.w,b.w));
}
__device__ __forceinline__ float4 vmin3(float4 a, float4 b, float4 c) { return vmin(vmin(a,b),c); }
__device__ __forceinline__ float4 vmax3(float4 a, float4 b, float4 c) { return vmax(vmax(a,b),c); }

__device__ __forceinline__ float4 hmin_shfl(float4 a, int tx) {
    float aL = __shfl_up_sync(0xffffffffu, a.w, 1);
    float aR = __shfl_down_sync(0xffffffffu, a.x, 1);
    if (tx == 0)  aL = a.x;
    if (tx == 31) aR = a.w;
    float m01 = fminf(a.x, a.y), m12 = fminf(a.y, a.z), m23 = fminf(a.z, a.w);
    return make_float4(fminf(aL, m01), fminf(m01, a.z), fminf(m12, a.w), fminf(m23, aR));
}
__device__ __forceinline__ float4 hmax_shfl(float4 a, int tx) {
    float aL = __shfl_up_sync(0xffffffffu, a.w, 1);
    float aR = __shfl_down_sync(0xffffffffu, a.x, 1);
    if (tx == 0)  aL = a.x;
    if (tx == 31) aR = a.w;
    float m01 = fmaxf(a.x, a.y), m12 = fmaxf(a.y, a.z), m23 = fmaxf(a.z, a.w);
    return make_float4(fmaxf(aL, m01), fmaxf(m01, a.z), fmaxf(m12, a.w), fmaxf(m23, aR));
}

__global__ void zero_acc_kernel() {
    if (threadIdx.x < 8) g_acc[threadIdx.x] = 0.f;
}

// ---------------------------------------------------------------------------
// prep
// ---------------------------------------------------------------------------
__global__ __launch_bounds__(256) void prep_kernel(const float* __restrict__ pred,
                                                   const float* __restrict__ tru) {
    __shared__ float sm[3][8];
    const float4* p4 = (const float4*)pred;
    const float4* t4 = (const float4*)tru;
    float4* y4 = (float4*)g_yp;
    int base = blockIdx.x * 1024 + threadIdx.x;
    float st = 0.f, sp = 0.f, stp = 0.f;
#pragma unroll
    for (int k = 0; k < 4; k++) {
        int i = base + k * 256;
        float4 t = t4[i];
        float4 x = p4[i];
        float4 p;
        p.x = 1.f / (1.f + __expf(-x.x));
        p.y = 1.f / (1.f + __expf(-x.y));
        p.z = 1.f / (1.f + __expf(-x.z));
        p.w = 1.f / (1.f + __expf(-x.w));
        y4[i] = p;
        st  += (t.x + t.y) + (t.z + t.w);
        sp  += (p.x + p.y) + (p.z + p.w);
        stp += (t.x*p.x + t.y*p.y) + (t.z*p.z + t.w*p.w);
    }
#pragma unroll
    for (int o = 16; o > 0; o >>= 1) {
        st  += __shfl_xor_sync(0xffffffffu, st,  o);
        sp  += __shfl_xor_sync(0xffffffffu, sp,  o);
        stp += __shfl_xor_sync(0xffffffffu, stp, o);
    }
    int w = threadIdx.x >> 5, lane = threadIdx.x & 31;
    if (lane == 0) { sm[0][w] = st; sm[1][w] = sp; sm[2][w] = stp; }
    __syncthreads();
    if (threadIdx.x == 0) {
        float a = 0.f, b = 0.f, c = 0.f;
#pragma unroll
        for (int i = 0; i < 8; i++) { a += sm[0][i]; b += sm[1][i]; c += sm[2][i]; }
        atomicAdd(&g_acc[0], a); atomicAdd(&g_acc[1], b); atomicAdd(&g_acc[2], c);
    }
}

// ---------------------------------------------------------------------------
// init: skel = relu(x - dilate(erode(x)))  (R3 style, 2 syncs/plane)
// ---------------------------------------------------------------------------
__global__ __launch_bounds__(1024) void init_kernel(int inSel, const float* __restrict__ extIn) {
    __shared__ float4 As[32][32];
    __shared__ float4 Ms[32][32];
    const float* __restrict__ x = pick(inSel, extIn);

    const int tx = threadIdx.x, ty = threadIdx.y;
    const int b   = blockIdx.z;
    const int oz0 = blockIdx.y * ZLEN;
    const int oz1 = min(oz0 + ZLEN, VOL);
    const int gy  = blockIdx.x * OTY - 3 + ty;
    const bool vrow = (gy >= 0 && gy < VOL);
    const bool wr   = vrow && ty >= 3 && ty < 29;
    const int ym = ty > 0 ? ty - 1 : 0, yp = ty < 31 ? ty + 1 : 31;
    const int bOff = b * VOL3;
    const int rowOff = bOff + (vrow ? gy : 0) * VOL + tx * 4;

    float4 a_m1 = f4(PINF), a_m2 = f4(PINF), bxy_m1 = f4(PINF);
    float4 m_m1 = f4(NINF), m_m2 = f4(NINF);

    int z0 = oz0 - 2;
    float4 cur = f4(PINF);
    if (vrow && (unsigned)z0 < (unsigned)VOL)
        cur = *(const float4*)(x + z0 * VOL2 + rowOff);
    As[ty][tx] = cur;
    __syncthreads();

    for (int z = z0; z <= oz1 + 1; ++z) {
        float4 nxt = f4(PINF);
        if (vrow && (unsigned)(z + 1) < (unsigned)VOL)
            nxt = *(const float4*)(x + (z + 1) * VOL2 + rowOff);

        float4 up = As[ym][tx], dn = As[yp][tx];
        float4 h  = hmin_shfl(cur, tx);
        float4 bxy = vmin3(h, up, dn);
        float4 e1 = vmin3(a_m2, cur, bxy_m1);
        if (!vrow || (unsigned)(z - 1) >= (unsigned)VOL) e1 = f4(NINF);
        float4 hm = hmax_shfl(e1, tx);
        Ms[ty][tx] = hm;
        __syncthreads();
        As[ty][tx] = nxt;
        float4 mxy = vmax3(hm, Ms[ym][tx], Ms[yp][tx]);
        int zo = z - 2;
        if (wr && zo >= oz0 && zo < oz1) {
            float4 openv = vmax3(m_m2, m_m1, mxy);
            float4 s;
            s.x = fmaxf(a_m2.x - openv.x, 0.f);
            s.y = fmaxf(a_m2.y - openv.y, 0.f);
            s.z = fmaxf(a_m2.z - openv.z, 0.f);
            s.w = fmaxf(a_m2.w - openv.w, 0.f);
            *(float4*)(g_skel + zo * VOL2 + rowOff) = s;
        }
        __syncthreads();
        a_m2 = a_m1; a_m1 = cur; bxy_m1 = bxy;
        m_m2 = m_m1; m_m1 = mxy;
        cur = nxt;
    }
}

// ---------------------------------------------------------------------------
// iter: ONE barrier per plane. Shared-memory ring buffers hold all z-history:
//   As ring[4]: input planes          (write a(z+1), read plane z up/dn, a(z-2) own)
//   Es ring[4]: e1 planes             (write e1(z-1), read e1(z-2) own/up/dn, e1(z-4) own)
//   Ms ring[2]: row-hmax of e2 planes (write hm(z-2), read hm(z-3) up/dn)
// Registers: cur=a(z), nxtHold=a(z+1), bxy_m1, E2=e1(z-3), hm_m1=hm(z-3),
//            m_m1=mxy(z-4), m_m2=mxy(z-5). Output at zo=z-4.
// ---------------------------------------------------------------------------
__global__ __launch_bounds__(1024) void iter_kernel(
    int inSel, const float* __restrict__ extIn, int outSel,
    int doSum, int otherSel, const float* __restrict__ extOther, int accBase)
{
    extern __shared__ float4 smem[];   // 10 * 1024 float4 = 160 KB
    const int AS0 = 0, ES0 = 4096, MS0 = 8192;

    const float* __restrict__ imgIn = pick(inSel, extIn);
    float* imgOut = (outSel == 0) ? g_imgA : g_imgB;
    const float* __restrict__ other = pick(otherSel, extOther);

    const int tx = threadIdx.x, ty = threadIdx.y;
    const int b   = blockIdx.z;
    const int oz0 = blockIdx.y * ZLEN;
    const int oz1 = min(oz0 + ZLEN, VOL);
    const int gy  = blockIdx.x * OTY - 3 + ty;
    const bool vrow = (gy >= 0 && gy < VOL);
    const bool wr   = vrow && ty >= 3 && ty < 29;
    const int ym = ty > 0 ? ty - 1 : 0, yp = ty < 31 ? ty + 1 : 31;
    const int bOff = b * VOL3;
    const int rowOff = bOff + (vrow ? gy : 0) * VOL + tx * 4;
    const int sIdx = ty * 32 + tx;

    float4 bxy_m1 = f4(PINF);
    float4 E2 = f4(PINF);                 // e1(z-3)
    float4 hm_m1 = f4(NINF);              // hm(z-3)
    float4 m_m1 = f4(NINF), m_m2 = f4(NINF);
    float sumS = 0.f, sumC = 0.f;

    const int z0 = oz0 - 3;
    float4 cur = f4(PINF), nxtHold = f4(PINF);
    if (vrow && (unsigned)z0 < (unsigned)VOL)
        cur = *(const float4*)(imgIn + z0 * VOL2 + rowOff);
    if (vrow && (unsigned)(z0 + 1) < (unsigned)VOL)
        nxtHold = *(const float4*)(imgIn + (z0 + 1) * VOL2 + rowOff);

    // Prefill rings
    smem[AS0 + ((z0 + 8) & 3) * 1024 + sIdx] = cur;
#pragma unroll
    for (int s = 0; s < 4; s++) smem[ES0 + s * 1024 + sIdx] = f4(PINF);
    smem[MS0 + sIdx]        = f4(NINF);
    smem[MS0 + 1024 + sIdx] = f4(NINF);
    __syncthreads();

    for (int z = z0; z <= oz1 + 3; ++z) {
        // ring offsets (scalar arithmetic, no pointer arrays)
        const int aW  = AS0 + ((z + 9) & 3) * 1024;   // plane z+1 (write)
        const int aC  = AS0 + ((z + 8) & 3) * 1024;   // plane z (up/dn)
        const int aM2 = AS0 + ((z + 6) & 3) * 1024;   // plane z-2 (own)
        const int eW  = ES0 + ((z + 7) & 3) * 1024;   // e1(z-1) (write)
        const int eR  = ES0 + ((z + 6) & 3) * 1024;   // e1(z-2) (own/up/dn)
        const int eM4 = ES0 + ((z + 4) & 3) * 1024;   // e1(z-4) (own)
        const int mW  = MS0 + ((z + 6) & 1) * 1024;   // hm(z-2) (write)
        const int mR  = MS0 + ((z + 5) & 1) * 1024;   // hm(z-3) (up/dn)

        const int zo = z - 4;
        const bool doOut = wr && zo >= oz0 && zo < oz1;
        const int gi = zo * VOL2 + rowOff;

        // global prefetches (consumed late this iteration)
        float4 nxt2 = f4(PINF);
        if (vrow && (unsigned)(z + 2) < (unsigned)VOL)
            nxt2 = *(const float4*)(imgIn + (z + 2) * VOL2 + rowOff);
        float4 sPre = f4(0.f);
        if (doOut) sPre = *(const float4*)(g_skel + gi);

        // ring write: plane z+1
        smem[aW + sIdx] = nxtHold;

        // stage 1: bxy(z), e1(z-1)
        float4 up = smem[aC + ym * 32 + tx], dn = smem[aC + yp * 32 + tx];
        float4 am2 = smem[aM2 + sIdx];
        float4 bxy = vmin3(hmin_shfl(cur, tx), up, dn);
        float4 e1 = vmin3(am2, cur, bxy_m1);
        if (!vrow || (unsigned)(z - 1) >= (unsigned)VOL) e1 = f4(PINF);
        smem[eW + sIdx] = e1;

        // stage 2: cxy(z-2), e2(z-2), hm(z-2)
        float4 esOwn = smem[eR + sIdx];
        float4 esU = smem[eR + ym * 32 + tx], esD = smem[eR + yp * 32 + tx];
        float4 cxy = vmin3(hmin_shfl(esOwn, tx), esU, esD);
        float4 e2 = vmin3(cxy, E2, e1);
        if (!vrow || (unsigned)(z - 2) >= (unsigned)VOL) e2 = f4(NINF);
        float4 hm = hmax_shfl(e2, tx);
        smem[mW + sIdx] = hm;

        // stage 3: mxy(z-3)
        float4 msU = smem[mR + ym * 32 + tx], msD = smem[mR + yp * 32 + tx];
        float4 mxy = vmax3(hm_m1, msU, msD);

        // output at zo = z-4
        if (doOut) {
            float4 imgN = smem[eM4 + sIdx];          // e1(zo)
            float4 openv = vmax3(m_m2, m_m1, mxy);
            float4 delta;
            delta.x = fmaxf(imgN.x - openv.x, 0.f);
            delta.y = fmaxf(imgN.y - openv.y, 0.f);
            delta.z = fmaxf(imgN.z - openv.z, 0.f);
            delta.w = fmaxf(imgN.w - openv.w, 0.f);
            float4 s = sPre;
            s.x += fmaxf(fmaf(-s.x, delta.x, delta.x), 0.f);
            s.y += fmaxf(fmaf(-s.y, delta.y, delta.y), 0.f);
            s.z += fmaxf(fmaf(-s.z, delta.z, delta.z), 0.f);
            s.w += fmaxf(fmaf(-s.w, delta.w, delta.w), 0.f);
            *(float4*)(g_skel + gi) = s;
            *(float4*)(imgOut + gi) = imgN;
            if (doSum) {
                float4 o = *(const float4*)(other + gi);
                sumS += (s.x + s.y) + (s.z + s.w);
                sumC += (s.x*o.x + s.y*o.y) + (s.z*o.z + s.w*o.w);
            }
        }

        __syncthreads();

        // shift registers
        cur = nxtHold; nxtHold = nxt2;
        bxy_m1 = bxy;
        E2 = esOwn;
        hm_m1 = hm;
        m_m2 = m_m1; m_m1 = mxy;
    }

    if (doSum) {
#pragma unroll
        for (int o = 16; o > 0; o >>= 1) {
            sumS += __shfl_xor_sync(0xffffffffu, sumS, o);
            sumC += __shfl_xor_sync(0xffffffffu, sumC, o);
        }
        int w = sIdx >> 5, lane = sIdx & 31;
        float* red = (float*)smem;
        if (lane == 0) { red[w] = sumS; red[32 + w] = sumC; }
        __syncthreads();
        if (w == 0) {
            float s = red[lane], c = red[32 + lane];
#pragma unroll
            for (int o = 16; o > 0; o >>= 1) {
                s += __shfl_xor_sync(0xffffffffu, s, o);
                c += __shfl_xor_sync(0xffffffffu, c, o);
            }
            if (lane == 0) {
                atomicAdd(&g_acc[accBase], s);
                atomicAdd(&g_acc[accBase + 1], c);
            }
        }
    }
}

__global__ void final_kernel(float* out) {
    float st = g_acc[0], sp = g_acc[1], stp = g_acc[2];
    float skp = g_acc[3], skpt = g_acc[4], skt = g_acc[5], sktp = g_acc[6];
    float dice = 1.f - (2.f * stp + 1.f) / (st + sp + 1.f);
    float tprec = (skpt + 1.f) / (skp + 1.f);
    float tsens = (sktp + 1.f) / (skt + 1.f);
    float cl = 1.f - 2.f * (tprec * tsens) / (tprec + tsens);
    out[0] = 0.7f * dice + 0.3f * cl;
}

#define ITER_SMEM (10 * 1024 * 16)   // 160 KB

extern "C" void kernel_launch(void* const* d_in, const int* in_sizes, int n_in,
                              void* d_out, int out_size) {
    const float* pred = (const float*)d_in[0];
    const float* tru  = (const float*)d_in[1];
    float* out = (float*)d_out;

    static int smem_set = 0;
    if (!smem_set) {
        cudaFuncSetAttribute(iter_kernel, cudaFuncAttributeMaxDynamicSharedMemorySize, ITER_SMEM);
        smem_set = 1;
    }

    dim3 blk(32, 32);
    dim3 grd(NTY, ZSEG, NB);

    zero_acc_kernel<<<1, 32>>>();
    prep_kernel<<<NVOX / 4096, 256>>>(pred, tru);

    // ---- pred skeleton ----
    init_kernel<<<grd, blk>>>(2, nullptr);
    iter_kernel<<<grd, blk, ITER_SMEM>>>(2, nullptr, 0, 0, 0, nullptr, 0);
    for (int k = 2; k <= 16; ++k) {
        int inSel  = (k & 1) ? 1 : 0;
        int outSel = (k & 1) ? 0 : 1;
        int doSum  = (k == 16) ? 1 : 0;
        iter_kernel<<<grd, blk, ITER_SMEM>>>(inSel, nullptr, outSel, doSum, 3, tru, 3);
    }

    // ---- true skeleton ----
    init_kernel<<<grd, blk>>>(3, tru);
    iter_kernel<<<grd, blk, ITER_SMEM>>>(3, tru, 0, 0, 0, nullptr, 0);
    for (int k = 2; k <= 16; ++k) {
        int inSel  = (k & 1) ? 1 : 0;
        int outSel = (k & 1) ? 0 : 1;
        int doSum  = (k == 16) ? 1 : 0;
        iter_kernel<<<grd, blk, ITER_SMEM>>>(inSel, nullptr, outSel, doSum, 2, nullptr, 5);
    }

    final_kernel<<<1, 1>>>(out);
}

// round 8
// speedup vs baseline: 2.7727x; 1.2731x over previous
#include <cuda_runtime.h>
#include <math.h>

#define VOL   128
#define VOL2  (VOL*VOL)
#define VOL3  (VOL*VOL*VOL)
#define NB    4
#define NVOX  (NB*VOL3)
#define OTY   26              // output rows per block tile (y)
#define NTY   5               // ceil(128/26)
#define ZSEG  7               // 140 blocks = 1 wave
#define ZLEN  19

#define PINF __int_as_float(0x7f800000)
#define NINF __int_as_float(0xff800000)

__device__ float g_yp[NVOX];
__device__ float g_imgA[NVOX];
__device__ float g_imgB[NVOX];
__device__ float g_skel[NVOX];
__device__ float g_acc[8];

__device__ __forceinline__ const float* pick(int sel, const float* ext) {
    if (sel == 0) return g_imgA;
    if (sel == 1) return g_imgB;
    if (sel == 2) return g_yp;
    return ext;
}

__device__ __forceinline__ float4 f4(float v) { return make_float4(v, v, v, v); }
__device__ __forceinline__ float4 vmin(float4 a, float4 b) {
    return make_float4(fminf(a.x,b.x), fminf(a.y,b.y), fminf(a.z,b.z), fminf(a.w,b.w));
}
__device__ __forceinline__ float4 vmax(float4 a, float4 b) {
    return make_float4(fmaxf(a.x,b.x), fmaxf(a.y,b.y), fmaxf(a.z,b.z), fmaxf(a.w,b.w));
}
__device__ __forceinline__ float4 vmin3(float4 a, float4 b, float4 c) { return vmin(vmin(a,b),c); }
__device__ __forceinline__ float4 vmax3(float4 a, float4 b, float4 c) { return vmax(vmax(a,b),c); }

__device__ __forceinline__ float4 hmin_shfl(float4 a, int tx) {
    float aL = __shfl_up_sync(0xffffffffu, a.w, 1);
    float aR = __shfl_down_sync(0xffffffffu, a.x, 1);
    if (tx == 0)  aL = a.x;
    if (tx == 31) aR = a.w;
    float m01 = fminf(a.x, a.y), m12 = fminf(a.y, a.z), m23 = fminf(a.z, a.w);
    return make_float4(fminf(aL, m01), fminf(m01, a.z), fminf(m12, a.w), fminf(m23, aR));
}
__device__ __forceinline__ float4 hmax_shfl(float4 a, int tx) {
    float aL = __shfl_up_sync(0xffffffffu, a.w, 1);
    float aR = __shfl_down_sync(0xffffffffu, a.x, 1);
    if (tx == 0)  aL = a.x;
    if (tx == 31) aR = a.w;
    float m01 = fmaxf(a.x, a.y), m12 = fmaxf(a.y, a.z), m23 = fmaxf(a.z, a.w);
    return make_float4(fmaxf(aL, m01), fmaxf(m01, a.z), fmaxf(m12, a.w), fmaxf(m23, aR));
}

__global__ void zero_acc_kernel() {
    if (threadIdx.x < 8) g_acc[threadIdx.x] = 0.f;
}

// ---------------------------------------------------------------------------
// prep
// ---------------------------------------------------------------------------
__global__ __launch_bounds__(256) void prep_kernel(const float* __restrict__ pred,
                                                   const float* __restrict__ tru) {
    __shared__ float sm[3][8];
    const float4* p4 = (const float4*)pred;
    const float4* t4 = (const float4*)tru;
    float4* y4 = (float4*)g_yp;
    int base = blockIdx.x * 1024 + threadIdx.x;
    float st = 0.f, sp = 0.f, stp = 0.f;
#pragma unroll
    for (int k = 0; k < 4; k++) {
        int i = base + k * 256;
        float4 t = t4[i];
        float4 x = p4[i];
        float4 p;
        p.x = 1.f / (1.f + __expf(-x.x));
        p.y = 1.f / (1.f + __expf(-x.y));
        p.z = 1.f / (1.f + __expf(-x.z));
        p.w = 1.f / (1.f + __expf(-x.w));
        y4[i] = p;
        st  += (t.x + t.y) + (t.z + t.w);
        sp  += (p.x + p.y) + (p.z + p.w);
        stp += (t.x*p.x + t.y*p.y) + (t.z*p.z + t.w*p.w);
    }
#pragma unroll
    for (int o = 16; o > 0; o >>= 1) {
        st  += __shfl_xor_sync(0xffffffffu, st,  o);
        sp  += __shfl_xor_sync(0xffffffffu, sp,  o);
        stp += __shfl_xor_sync(0xffffffffu, stp, o);
    }
    int w = threadIdx.x >> 5, lane = threadIdx.x & 31;
    if (lane == 0) { sm[0][w] = st; sm[1][w] = sp; sm[2][w] = stp; }
    __syncthreads();
    if (threadIdx.x == 0) {
        float a = 0.f, b = 0.f, c = 0.f;
#pragma unroll
        for (int i = 0; i < 8; i++) { a += sm[0][i]; b += sm[1][i]; c += sm[2][i]; }
        atomicAdd(&g_acc[0], a); atomicAdd(&g_acc[1], b); atomicAdd(&g_acc[2], c);
    }
}

// ---------------------------------------------------------------------------
// init: skel = relu(x - dilate(erode(x)))  AND  g_imgA = erode(x)
// ---------------------------------------------------------------------------
__global__ __launch_bounds__(1024) void init_kernel(int inSel, const float* __restrict__ extIn) {
    __shared__ float4 As[32][32];
    __shared__ float4 Ms[32][32];
    const float* __restrict__ x = pick(inSel, extIn);

    const int tx = threadIdx.x, ty = threadIdx.y;
    const int b   = blockIdx.z;
    const int oz0 = blockIdx.y * ZLEN;
    const int oz1 = min(oz0 + ZLEN, VOL);
    const int gy  = blockIdx.x * OTY - 3 + ty;
    const bool vrow = (gy >= 0 && gy < VOL);
    const bool wr   = vrow && ty >= 3 && ty < 29;
    const int ym = ty > 0 ? ty - 1 : 0, yp = ty < 31 ? ty + 1 : 31;
    const int bOff = b * VOL3;
    const int rowOff = bOff + (vrow ? gy : 0) * VOL + tx * 4;

    float4 a_m1 = f4(PINF), a_m2 = f4(PINF), bxy_m1 = f4(PINF);
    float4 m_m1 = f4(NINF), m_m2 = f4(NINF);
    float4 e1_m1 = f4(PINF);           // e1(z-2) carry (true erosion value)

    int z0 = oz0 - 2;
    float4 cur = f4(PINF);
    if (vrow && (unsigned)z0 < (unsigned)VOL)
        cur = *(const float4*)(x + z0 * VOL2 + rowOff);
    As[ty][tx] = cur;
    __syncthreads();

    for (int z = z0; z <= oz1 + 1; ++z) {
        float4 nxt = f4(PINF);
        if (vrow && (unsigned)(z + 1) < (unsigned)VOL)
            nxt = *(const float4*)(x + (z + 1) * VOL2 + rowOff);

        float4 up = As[ym][tx], dn = As[yp][tx];
        float4 h  = hmin_shfl(cur, tx);
        float4 bxy = vmin3(h, up, dn);
        float4 e1 = vmin3(a_m2, cur, bxy_m1);              // erode at z-1 (true value)
        float4 e1d = e1;
        if (!vrow || (unsigned)(z - 1) >= (unsigned)VOL) e1d = f4(NINF);
        float4 hm = hmax_shfl(e1d, tx);
        Ms[ty][tx] = hm;
        __syncthreads();
        As[ty][tx] = nxt;
        float4 mxy = vmax3(hm, Ms[ym][tx], Ms[yp][tx]);
        int zo = z - 2;
        if (wr && zo >= oz0 && zo < oz1) {
            float4 openv = vmax3(m_m2, m_m1, mxy);
            float4 s;
            s.x = fmaxf(a_m2.x - openv.x, 0.f);
            s.y = fmaxf(a_m2.y - openv.y, 0.f);
            s.z = fmaxf(a_m2.z - openv.z, 0.f);
            s.w = fmaxf(a_m2.w - openv.w, 0.f);
            int gi = zo * VOL2 + rowOff;
            *(float4*)(g_skel + gi) = s;
            *(float4*)(g_imgA + gi) = e1_m1;               // erode(x) at zo
        }
        __syncthreads();
        a_m2 = a_m1; a_m1 = cur; bxy_m1 = bxy;
        m_m2 = m_m1; m_m1 = mxy;
        e1_m1 = e1;
        cur = nxt;
    }
}

// ---------------------------------------------------------------------------
// iter (2-stage): input imgE_k = erode^k(x).
//   e2 = erode(imgE_k) = imgE_{k+1}; open = dilate(e2);
//   delta = relu(imgE_k - open); skel update; write e2.
// ONE barrier per plane. As ring[8] holds imgE planes; Ms ring[2] holds hm(e2).
// Loop var z: writes As(z+1); computes bxy(z), e2(z-1), hm(z-1), mxy(z-2);
// output at zo = z-3 (imgE(zo) own from ring, e2(zo) from register carry).
// ---------------------------------------------------------------------------
__global__ __launch_bounds__(1024) void iter_kernel(
    int inSel, const float* __restrict__ extIn, int outSel,
    int doSum, int otherSel, const float* __restrict__ extOther, int accBase)
{
    extern __shared__ float4 smem[];   // 8*1024 (As) + 2*1024 (Ms) = 160 KB
    const int AS0 = 0, MS0 = 8192;

    const float* __restrict__ imgIn = pick(inSel, extIn);
    float* imgOut = (outSel == 0) ? g_imgA : g_imgB;
    const float* __restrict__ other = pick(otherSel, extOther);

    const int tx = threadIdx.x, ty = threadIdx.y;
    const int b   = blockIdx.z;
    const int oz0 = blockIdx.y * ZLEN;
    const int oz1 = min(oz0 + ZLEN, VOL);
    const int gy  = blockIdx.x * OTY - 3 + ty;
    const bool vrow = (gy >= 0 && gy < VOL);
    const bool wr   = vrow && ty >= 3 && ty < 29;
    const int ym = ty > 0 ? ty - 1 : 0, yp = ty < 31 ? ty + 1 : 31;
    const int bOff = b * VOL3;
    const int rowOff = bOff + (vrow ? gy : 0) * VOL + tx * 4;
    const int sIdx = ty * 32 + tx;

    float4 bxy_m1 = f4(PINF);
    float4 e2_m1 = f4(PINF), e2_m2 = f4(PINF);   // e2(z-2), e2(z-3) true erosion
    float4 hm_m1 = f4(NINF);                      // hm(z-2)
    float4 m_m1 = f4(NINF), m_m2 = f4(NINF);      // mxy(z-3), mxy(z-4)
    float sumS = 0.f, sumC = 0.f;

    const int z0 = oz0 - 2;
    float4 cur = f4(PINF), nxtHold = f4(PINF);
    if (vrow && (unsigned)z0 < (unsigned)VOL)
        cur = *(const float4*)(imgIn + z0 * VOL2 + rowOff);
    if (vrow && (unsigned)(z0 + 1) < (unsigned)VOL)
        nxtHold = *(const float4*)(imgIn + (z0 + 1) * VOL2 + rowOff);

    smem[AS0 + ((z0 + 8) & 7) * 1024 + sIdx] = cur;
    smem[MS0 + sIdx]        = f4(NINF);
    smem[MS0 + 1024 + sIdx] = f4(NINF);
    __syncthreads();

    for (int z = z0; z <= oz1 + 2; ++z) {
        const int aW  = AS0 + ((z + 9) & 7) * 1024;   // imgE(z+1) write
        const int aC  = AS0 + ((z + 8) & 7) * 1024;   // imgE(z) up/dn
        const int aM2 = AS0 + ((z + 6) & 7) * 1024;   // imgE(z-2) own
        const int aM3 = AS0 + ((z + 5) & 7) * 1024;   // imgE(z-3) own
        const int mW  = MS0 + ((z + 7) & 1) * 1024;   // hm(z-1) write
        const int mR  = MS0 + ((z + 6) & 1) * 1024;   // hm(z-2) up/dn

        const int zo = z - 3;
        const bool doOut = wr && zo >= oz0 && zo < oz1;
        const int gi = zo * VOL2 + rowOff;

        // global prefetches
        float4 nxt2 = f4(PINF);
        if (vrow && (unsigned)(z + 2) < (unsigned)VOL)
            nxt2 = *(const float4*)(imgIn + (z + 2) * VOL2 + rowOff);
        float4 sPre = f4(0.f);
        if (doOut) sPre = *(const float4*)(g_skel + gi);

        smem[aW + sIdx] = nxtHold;

        // stage 1: erosion e2(z-1)
        float4 up = smem[aC + ym * 32 + tx], dn = smem[aC + yp * 32 + tx];
        float4 bxy = vmin3(hmin_shfl(cur, tx), up, dn);
        float4 am2 = smem[aM2 + sIdx];
        float4 e2 = vmin3(am2, cur, bxy_m1);              // true erosion at z-1
        float4 e2d = e2;
        if (!vrow || (unsigned)(z - 1) >= (unsigned)VOL) e2d = f4(NINF);
        float4 hm = hmax_shfl(e2d, tx);
        smem[mW + sIdx] = hm;

        // stage 2: in-plane 3x3 max at z-2
        float4 mxy = vmax3(hm_m1, smem[mR + ym * 32 + tx], smem[mR + yp * 32 + tx]);

        // output at zo = z-3
        if (doOut) {
            float4 imgE = smem[aM3 + sIdx];               // input image at zo
            float4 openv = vmax3(m_m2, m_m1, mxy);        // dilate(e2) at zo
            float4 delta;
            delta.x = fmaxf(imgE.x - openv.x, 0.f);
            delta.y = fmaxf(imgE.y - openv.y, 0.f);
            delta.z = fmaxf(imgE.z - openv.z, 0.f);
            delta.w = fmaxf(imgE.w - openv.w, 0.f);
            float4 s = sPre;
            s.x += fmaxf(fmaf(-s.x, delta.x, delta.x), 0.f);
            s.y += fmaxf(fmaf(-s.y, delta.y, delta.y), 0.f);
            s.z += fmaxf(fmaf(-s.z, delta.z, delta.z), 0.f);
            s.w += fmaxf(fmaf(-s.w, delta.w, delta.w), 0.f);
            *(float4*)(g_skel + gi) = s;
            if (!doSum) *(float4*)(imgOut + gi) = e2_m2;  // imgE_{k+1}(zo); skip on last iter
            if (doSum) {
                float4 o = *(const float4*)(other + gi);
                sumS += (s.x + s.y) + (s.z + s.w);
                sumC += (s.x*o.x + s.y*o.y) + (s.z*o.z + s.w*o.w);
            }
        }

        __syncthreads();

        cur = nxtHold; nxtHold = nxt2;
        bxy_m1 = bxy;
        e2_m2 = e2_m1; e2_m1 = e2;
        hm_m1 = hm;
        m_m2 = m_m1; m_m1 = mxy;
    }

    if (doSum) {
#pragma unroll
        for (int o = 16; o > 0; o >>= 1) {
            sumS += __shfl_xor_sync(0xffffffffu, sumS, o);
            sumC += __shfl_xor_sync(0xffffffffu, sumC, o);
        }
        int w = sIdx >> 5, lane = sIdx & 31;
        float* red = (float*)smem;
        if (lane == 0) { red[w] = sumS; red[32 + w] = sumC; }
        __syncthreads();
        if (w == 0) {
            float s = red[lane], c = red[32 + lane];
#pragma unroll
            for (int o = 16; o > 0; o >>= 1) {
                s += __shfl_xor_sync(0xffffffffu, s, o);
                c += __shfl_xor_sync(0xffffffffu, c, o);
            }
            if (lane == 0) {
                atomicAdd(&g_acc[accBase], s);
                atomicAdd(&g_acc[accBase + 1], c);
            }
        }
    }
}

__global__ void final_kernel(float* out) {
    float st = g_acc[0], sp = g_acc[1], stp = g_acc[2];
    float skp = g_acc[3], skpt = g_acc[4], skt = g_acc[5], sktp = g_acc[6];
    float dice = 1.f - (2.f * stp + 1.f) / (st + sp + 1.f);
    float tprec = (skpt + 1.f) / (skp + 1.f);
    float tsens = (sktp + 1.f) / (skt + 1.f);
    float cl = 1.f - 2.f * (tprec * tsens) / (tprec + tsens);
    out[0] = 0.7f * dice + 0.3f * cl;
}

#define ITER_SMEM (10 * 1024 * 16)   // 160 KB

extern "C" void kernel_launch(void* const* d_in, const int* in_sizes, int n_in,
                              void* d_out, int out_size) {
    const float* pred = (const float*)d_in[0];
    const float* tru  = (const float*)d_in[1];
    float* out = (float*)d_out;

    static int smem_set = 0;
    if (!smem_set) {
        cudaFuncSetAttribute(iter_kernel, cudaFuncAttributeMaxDynamicSharedMemorySize, ITER_SMEM);
        smem_set = 1;
    }

    dim3 blk(32, 32);
    dim3 grd(NTY, ZSEG, NB);

    zero_acc_kernel<<<1, 32>>>();
    prep_kernel<<<NVOX / 4096, 256>>>(pred, tru);

    // ---- pred skeleton: init writes skel0 + imgA = erode(yp) ----
    init_kernel<<<grd, blk>>>(2, nullptr);
    for (int k = 1; k <= 16; ++k) {
        int inSel  = (k & 1) ? 0 : 1;     // odd reads A, even reads B
        int outSel = (k & 1) ? 1 : 0;
        int doSum  = (k == 16) ? 1 : 0;
        iter_kernel<<<grd, blk, ITER_SMEM>>>(inSel, nullptr, outSel, doSum, 3, tru, 3);
    }

    // ---- true skeleton ----
    init_kernel<<<grd, blk>>>(3, tru);
    for (int k = 1; k <= 16; ++k) {
        int inSel  = (k & 1) ? 0 : 1;
        int outSel = (k & 1) ? 1 : 0;
        int doSum  = (k == 16) ? 1 : 0;
        iter_kernel<<<grd, blk, ITER_SMEM>>>(inSel, nullptr, outSel, doSum, 2, nullptr, 5);
    }

    final_kernel<<<1, 1>>>(out);
}

// round 9
// speedup vs baseline: 4.2278x; 1.5248x over previous
#include <cuda_runtime.h>
#include <cuda_fp16.h>
#include <math.h>

#define VOL   128
#define VOL2  (VOL*VOL)
#define VOL3  (VOL*VOL*VOL)
#define NB    4
#define NVOX  (NB*VOL3)
#define NV4   (NVOX/4)
#define OTY   26
#define NTY   5
#define ZSEG  7               // 140 blocks = 1 wave
#define ZLEN  19

#define PINF __int_as_float(0x7f800000)
#define HPINF2 0x7C007C00u
#define HNINF2 0xFC00FC00u
#define FULLM 0xffffffffu

// fp16 chain buffers (uint2 = 4 half voxels)
__device__ uint2 g_yp16[NV4];
__device__ uint2 g_tru16[NV4];
__device__ uint2 g_imgA16[NV4];
__device__ uint2 g_imgB16[NV4];
__device__ float g_yp[NVOX];      // fp32 sigmoid (for tsens sum)
__device__ float g_skel[NVOX];
__device__ float g_acc[8];

__device__ __forceinline__ __half2 u2h(unsigned u) { return *reinterpret_cast<__half2*>(&u); }
__device__ __forceinline__ unsigned h2u(__half2 h) { return *reinterpret_cast<unsigned*>(&h); }

__device__ __forceinline__ uint2 hmin2u(uint2 a, uint2 b) {
    return make_uint2(h2u(__hmin2(u2h(a.x), u2h(b.x))), h2u(__hmin2(u2h(a.y), u2h(b.y))));
}
__device__ __forceinline__ uint2 hmax2u(uint2 a, uint2 b) {
    return make_uint2(h2u(__hmax2(u2h(a.x), u2h(b.x))), h2u(__hmax2(u2h(a.y), u2h(b.y))));
}
__device__ __forceinline__ uint2 hmin3u(uint2 a, uint2 b, uint2 c) { return hmin2u(hmin2u(a,b),c); }
__device__ __forceinline__ uint2 hmax3u(uint2 a, uint2 b, uint2 c) { return hmax2u(hmax2u(a,b),c); }

// x-window min over [x-1,x+1] for 4 packed halfs (v0..v3); clamp at volume edge
__device__ __forceinline__ uint2 hminS(uint2 v, int tx) {
    unsigned lb = __shfl_up_sync(FULLM, v.y, 1);     // left neighbor's (v2,v3)
    unsigned rn = __shfl_down_sync(FULLM, v.x, 1);   // right neighbor's (v0,v1)
    if (tx == 0)  lb = v.x << 16;                    // v_{-1} := v0
    if (tx == 31) rn = v.y >> 16;                    // v4 := v3
    unsigned Lb = __byte_perm(v.x, v.y, 0x5432);     // (v1,v2)
    unsigned La = __byte_perm(lb, v.x, 0x5432);      // (v-1,v0)
    unsigned Rb = __byte_perm(v.y, rn, 0x5432);      // (v3,v4)
    uint2 L = make_uint2(La, Lb), R = make_uint2(Lb, Rb);
    return hmin3u(L, v, R);
}
__device__ __forceinline__ uint2 hmaxS(uint2 v, int tx) {
    unsigned lb = __shfl_up_sync(FULLM, v.y, 1);
    unsigned rn = __shfl_down_sync(FULLM, v.x, 1);
    if (tx == 0)  lb = v.x << 16;
    if (tx == 31) rn = v.y >> 16;
    unsigned Lb = __byte_perm(v.x, v.y, 0x5432);
    unsigned La = __byte_perm(lb, v.x, 0x5432);
    unsigned Rb = __byte_perm(v.y, rn, 0x5432);
    uint2 L = make_uint2(La, Lb), R = make_uint2(Lb, Rb);
    return hmax3u(L, v, R);
}

__device__ __forceinline__ const uint2* pickH(int sel) {
    if (sel == 0) return g_imgA16;
    if (sel == 1) return g_imgB16;
    if (sel == 2) return g_yp16;
    return g_tru16;
}
__device__ __forceinline__ const float* pickF(int sel, const float* ext) {
    return (sel == 2) ? g_yp : ext;
}

__global__ void zero_acc_kernel() {
    if (threadIdx.x < 8) g_acc[threadIdx.x] = 0.f;
}

// ---------------------------------------------------------------------------
// prep: yp = sigmoid(pred) (fp32 + fp16), tru16 = fp16(tru); dice sums
// ---------------------------------------------------------------------------
__global__ __launch_bounds__(256) void prep_kernel(const float* __restrict__ pred,
                                                   const float* __restrict__ tru) {
    __shared__ float sm[3][8];
    const float4* p4 = (const float4*)pred;
    const float4* t4 = (const float4*)tru;
    float4* y4 = (float4*)g_yp;
    int base = blockIdx.x * 1024 + threadIdx.x;
    float st = 0.f, sp = 0.f, stp = 0.f;
#pragma unroll
    for (int k = 0; k < 4; k++) {
        int i = base + k * 256;
        float4 t = t4[i];
        float4 x = p4[i];
        float4 p;
        p.x = 1.f / (1.f + __expf(-x.x));
        p.y = 1.f / (1.f + __expf(-x.y));
        p.z = 1.f / (1.f + __expf(-x.z));
        p.w = 1.f / (1.f + __expf(-x.w));
        y4[i] = p;
        uint2 ph, th;
        ph.x = h2u(__halves2half2(__float2half_rn(p.x), __float2half_rn(p.y)));
        ph.y = h2u(__halves2half2(__float2half_rn(p.z), __float2half_rn(p.w)));
        th.x = h2u(__halves2half2(__float2half_rn(t.x), __float2half_rn(t.y)));
        th.y = h2u(__halves2half2(__float2half_rn(t.z), __float2half_rn(t.w)));
        g_yp16[i] = ph;
        g_tru16[i] = th;
        st  += (t.x + t.y) + (t.z + t.w);
        sp  += (p.x + p.y) + (p.z + p.w);
        stp += (t.x*p.x + t.y*p.y) + (t.z*p.z + t.w*p.w);
    }
#pragma unroll
    for (int o = 16; o > 0; o >>= 1) {
        st  += __shfl_xor_sync(FULLM, st,  o);
        sp  += __shfl_xor_sync(FULLM, sp,  o);
        stp += __shfl_xor_sync(FULLM, stp, o);
    }
    int w = threadIdx.x >> 5, lane = threadIdx.x & 31;
    if (lane == 0) { sm[0][w] = st; sm[1][w] = sp; sm[2][w] = stp; }
    __syncthreads();
    if (threadIdx.x == 0) {
        float a = 0.f, b = 0.f, c = 0.f;
#pragma unroll
        for (int i = 0; i < 8; i++) { a += sm[0][i]; b += sm[1][i]; c += sm[2][i]; }
        atomicAdd(&g_acc[0], a); atomicAdd(&g_acc[1], b); atomicAdd(&g_acc[2], c);
    }
}

// ---------------------------------------------------------------------------
// init: skel = relu(x - dilate(erode(x)))  AND  g_imgA16 = erode(x)   [fp16]
// ---------------------------------------------------------------------------
__global__ __launch_bounds__(1024) void init_kernel(int inSel) {
    __shared__ uint2 As[32][32];
    __shared__ uint2 Ms[32][32];
    const uint2* __restrict__ x = pickH(inSel);

    const int tx = threadIdx.x, ty = threadIdx.y;
    const int b   = blockIdx.z;
    const int oz0 = blockIdx.y * ZLEN;
    const int oz1 = min(oz0 + ZLEN, VOL);
    const int gy  = blockIdx.x * OTY - 3 + ty;
    const bool vrow = (gy >= 0 && gy < VOL);
    const bool wr   = vrow && ty >= 3 && ty < 29;
    const int ym = ty > 0 ? ty - 1 : 0, yp = ty < 31 ? ty + 1 : 31;
    const int rowOff4 = b * (VOL3/4) + (vrow ? gy : 0) * (VOL/4) + tx;

    const uint2 P2 = make_uint2(HPINF2, HPINF2);
    const uint2 N2 = make_uint2(HNINF2, HNINF2);

    uint2 a_m1 = P2, a_m2 = P2, bxy_m1 = P2;
    uint2 m_m1 = N2, m_m2 = N2;
    uint2 e1_m1 = P2;

    int z0 = oz0 - 2;
    uint2 cur = P2;
    if (vrow && (unsigned)z0 < (unsigned)VOL)
        cur = x[z0 * (VOL2/4) + rowOff4];
    As[ty][tx] = cur;
    __syncthreads();

    for (int z = z0; z <= oz1 + 1; ++z) {
        uint2 nxt = P2;
        if (vrow && (unsigned)(z + 1) < (unsigned)VOL)
            nxt = x[(z + 1) * (VOL2/4) + rowOff4];

        uint2 up = As[ym][tx], dn = As[yp][tx];
        uint2 bxy = hmin3u(hminS(cur, tx), up, dn);
        uint2 e1 = hmin3u(a_m2, cur, bxy_m1);             // erode at z-1
        uint2 e1d = e1;
        if (!vrow || (unsigned)(z - 1) >= (unsigned)VOL) e1d = N2;
        uint2 hm = hmaxS(e1d, tx);
        Ms[ty][tx] = hm;
        __syncthreads();
        As[ty][tx] = nxt;
        uint2 mxy = hmax3u(hm, Ms[ym][tx], Ms[yp][tx]);
        int zo = z - 2;
        if (wr && zo >= oz0 && zo < oz1) {
            uint2 openv = hmax3u(m_m2, m_m1, mxy);
            float2 x0 = __half22float2(u2h(a_m2.x)), x1 = __half22float2(u2h(a_m2.y));
            float2 o0 = __half22float2(u2h(openv.x)), o1 = __half22float2(u2h(openv.y));
            float4 s;
            s.x = fmaxf(x0.x - o0.x, 0.f);
            s.y = fmaxf(x0.y - o0.y, 0.f);
            s.z = fmaxf(x1.x - o1.x, 0.f);
            s.w = fmaxf(x1.y - o1.y, 0.f);
            int gi = zo * (VOL2/4) + rowOff4;
            ((float4*)g_skel)[gi] = s;
            g_imgA16[gi] = e1_m1;                          // erode(x) at zo
        }
        __syncthreads();
        a_m2 = a_m1; a_m1 = cur; bxy_m1 = bxy;
        m_m2 = m_m1; m_m1 = mxy;
        e1_m1 = e1;
        cur = nxt;
    }
}

// ---------------------------------------------------------------------------
// iter (fp16, 2-stage, 1 barrier/plane): e2 = erode(imgE_k); open = dilate(e2);
// skel update; write e2 as imgE_{k+1}. As ring[8], Ms ring[2]. Output zo=z-3.
// ---------------------------------------------------------------------------
__global__ __launch_bounds__(1024) void iter_kernel(
    int inSel, int outSel, int doSum, int otherSel,
    const float* __restrict__ extOther, int accBase)
{
    extern __shared__ uint2 smemU[];   // 8*1024 (As) + 2*1024 (Ms) = 80 KB
    const int AS0 = 0, MS0 = 8192;

    const uint2* __restrict__ imgIn = pickH(inSel);
    uint2* imgOut = (outSel == 0) ? g_imgA16 : g_imgB16;
    const float* __restrict__ other = pickF(otherSel, extOther);

    const int tx = threadIdx.x, ty = threadIdx.y;
    const int b   = blockIdx.z;
    const int oz0 = blockIdx.y * ZLEN;
    const int oz1 = min(oz0 + ZLEN, VOL);
    const int gy  = blockIdx.x * OTY - 3 + ty;
    const bool vrow = (gy >= 0 && gy < VOL);
    const bool wr   = vrow && ty >= 3 && ty < 29;
    const int ym = ty > 0 ? ty - 1 : 0, yp = ty < 31 ? ty + 1 : 31;
    const int rowOff4 = b * (VOL3/4) + (vrow ? gy : 0) * (VOL/4) + tx;
    const int sIdx = ty * 32 + tx;

    const uint2 P2 = make_uint2(HPINF2, HPINF2);
    const uint2 N2 = make_uint2(HNINF2, HNINF2);

    uint2 bxy_m1 = P2;
    uint2 e2_m1 = P2, e2_m2 = P2;     // e2(z-2), e2(z-3) true erosion
    uint2 hm_m1 = N2;                  // hm(z-2)
    uint2 m_m1 = N2, m_m2 = N2;        // mxy(z-3), mxy(z-4)
    float sumS = 0.f, sumC = 0.f;

    const int z0 = oz0 - 2;
    uint2 cur = P2, nxtHold = P2;
    if (vrow && (unsigned)z0 < (unsigned)VOL)
        cur = imgIn[z0 * (VOL2/4) + rowOff4];
    if (vrow && (unsigned)(z0 + 1) < (unsigned)VOL)
        nxtHold = imgIn[(z0 + 1) * (VOL2/4) + rowOff4];

    smemU[AS0 + ((z0 + 8) & 7) * 1024 + sIdx] = cur;
    smemU[MS0 + sIdx]        = N2;
    smemU[MS0 + 1024 + sIdx] = N2;
    __syncthreads();

    for (int z = z0; z <= oz1 + 2; ++z) {
        const int aW  = AS0 + ((z + 9) & 7) * 1024;   // imgE(z+1) write
        const int aC  = AS0 + ((z + 8) & 7) * 1024;   // imgE(z) up/dn
        const int aM2 = AS0 + ((z + 6) & 7) * 1024;   // imgE(z-2) own
        const int aM3 = AS0 + ((z + 5) & 7) * 1024;   // imgE(z-3) own
        const int mW  = MS0 + ((z + 7) & 1) * 1024;   // hm(z-1) write
        const int mR  = MS0 + ((z + 6) & 1) * 1024;   // hm(z-2) up/dn

        const int zo = z - 3;
        const bool doOut = wr && zo >= oz0 && zo < oz1;
        const int gi = zo * (VOL2/4) + rowOff4;

        uint2 nxt2 = P2;
        if (vrow && (unsigned)(z + 2) < (unsigned)VOL)
            nxt2 = imgIn[(z + 2) * (VOL2/4) + rowOff4];
        float4 sPre = make_float4(0.f, 0.f, 0.f, 0.f);
        if (doOut) sPre = ((const float4*)g_skel)[gi];

        smemU[aW + sIdx] = nxtHold;

        // stage 1: erosion e2(z-1)
        uint2 up = smemU[aC + ym * 32 + tx], dn = smemU[aC + yp * 32 + tx];
        uint2 bxy = hmin3u(hminS(cur, tx), up, dn);
        uint2 am2 = smemU[aM2 + sIdx];
        uint2 e2 = hmin3u(am2, cur, bxy_m1);
        uint2 e2d = e2;
        if (!vrow || (unsigned)(z - 1) >= (unsigned)VOL) e2d = N2;
        uint2 hm = hmaxS(e2d, tx);
        smemU[mW + sIdx] = hm;

        // stage 2: 3x3 in-plane max at z-2
        uint2 mxy = hmax3u(hm_m1, smemU[mR + ym * 32 + tx], smemU[mR + yp * 32 + tx]);

        // output at zo = z-3
        if (doOut) {
            uint2 imgE = smemU[aM3 + sIdx];
            uint2 openv = hmax3u(m_m2, m_m1, mxy);
            float2 i0 = __half22float2(u2h(imgE.x)),  i1 = __half22float2(u2h(imgE.y));
            float2 o0 = __half22float2(u2h(openv.x)), o1 = __half22float2(u2h(openv.y));
            float dx = fmaxf(i0.x - o0.x, 0.f);
            float dy = fmaxf(i0.y - o0.y, 0.f);
            float dz = fmaxf(i1.x - o1.x, 0.f);
            float dw = fmaxf(i1.y - o1.y, 0.f);
            float4 s = sPre;
            s.x += fmaxf(fmaf(-s.x, dx, dx), 0.f);
            s.y += fmaxf(fmaf(-s.y, dy, dy), 0.f);
            s.z += fmaxf(fmaf(-s.z, dz, dz), 0.f);
            s.w += fmaxf(fmaf(-s.w, dw, dw), 0.f);
            ((float4*)g_skel)[gi] = s;
            if (!doSum) {
                imgOut[gi] = e2_m2;
            } else {
                float4 o = ((const float4*)other)[gi];
                sumS += (s.x + s.y) + (s.z + s.w);
                sumC += (s.x*o.x + s.y*o.y) + (s.z*o.z + s.w*o.w);
            }
        }

        __syncthreads();

        cur = nxtHold; nxtHold = nxt2;
        bxy_m1 = bxy;
        e2_m2 = e2_m1; e2_m1 = e2;
        hm_m1 = hm;
        m_m2 = m_m1; m_m1 = mxy;
    }

    if (doSum) {
#pragma unroll
        for (int o = 16; o > 0; o >>= 1) {
            sumS += __shfl_xor_sync(FULLM, sumS, o);
            sumC += __shfl_xor_sync(FULLM, sumC, o);
        }
        int w = sIdx >> 5, lane = sIdx & 31;
        float* red = (float*)smemU;
        if (lane == 0) { red[w] = sumS; red[32 + w] = sumC; }
        __syncthreads();
        if (w == 0) {
            float s = red[lane], c = red[32 + lane];
#pragma unroll
            for (int o = 16; o > 0; o >>= 1) {
                s += __shfl_xor_sync(FULLM, s, o);
                c += __shfl_xor_sync(FULLM, c, o);
            }
            if (lane == 0) {
                atomicAdd(&g_acc[accBase], s);
                atomicAdd(&g_acc[accBase + 1], c);
            }
        }
    }
}

__global__ void final_kernel(float* out) {
    float st = g_acc[0], sp = g_acc[1], stp = g_acc[2];
    float skp = g_acc[3], skpt = g_acc[4], skt = g_acc[5], sktp = g_acc[6];
    float dice = 1.f - (2.f * stp + 1.f) / (st + sp + 1.f);
    float tprec = (skpt + 1.f) / (skp + 1.f);
    float tsens = (sktp + 1.f) / (skt + 1.f);
    float cl = 1.f - 2.f * (tprec * tsens) / (tprec + tsens);
    out[0] = 0.7f * dice + 0.3f * cl;
}

#define ITER_SMEM (10 * 1024 * 8)   // 80 KB

extern "C" void kernel_launch(void* const* d_in, const int* in_sizes, int n_in,
                              void* d_out, int out_size) {
    const float* pred = (const float*)d_in[0];
    const float* tru  = (const float*)d_in[1];
    float* out = (float*)d_out;

    static int smem_set = 0;
    if (!smem_set) {
        cudaFuncSetAttribute(iter_kernel, cudaFuncAttributeMaxDynamicSharedMemorySize, ITER_SMEM);
        smem_set = 1;
    }

    dim3 blk(32, 32);
    dim3 grd(NTY, ZSEG, NB);

    zero_acc_kernel<<<1, 32>>>();
    prep_kernel<<<NVOX / 4096, 256>>>(pred, tru);

    // ---- pred skeleton: init writes skel0 + imgA16 = erode(yp16) ----
    init_kernel<<<grd, blk>>>(2);
    for (int k = 1; k <= 16; ++k) {
        int inSel  = (k & 1) ? 0 : 1;
        int outSel = (k & 1) ? 1 : 0;
        int doSum  = (k == 16) ? 1 : 0;
        iter_kernel<<<grd, blk, ITER_SMEM>>>(inSel, outSel, doSum, 3, tru, 3);
    }

    // ---- true skeleton ----
    init_kernel<<<grd, blk>>>(3);
    for (int k = 1; k <= 16; ++k) {
        int inSel  = (k & 1) ? 0 : 1;
        int outSel = (k & 1) ? 1 : 0;
        int doSum  = (k == 16) ? 1 : 0;
        iter_kernel<<<grd, blk, ITER_SMEM>>>(inSel, outSel, doSum, 2, nullptr, 5);
    }

    final_kernel<<<1, 1>>>(out);
}

// round 10
// speedup vs baseline: 5.1332x; 1.2141x over previous
#include <cuda_runtime.h>
#include <cuda_fp16.h>
#include <math.h>

#define VOL   128
#define VOL2  (VOL*VOL)
#define VOL3  (VOL*VOL*VOL)
#define NB    4
#define NVOX  (NB*VOL3)
#define NV4   (NVOX/4)
#define OTY   26
#define NTY   5
#define ZSEG  7               // 140 blocks = 1 wave
#define ZLEN  19

#define HPINF2 0x7C007C00u
#define HNINF2 0xFC00FC00u
#define FULLM 0xffffffffu

// fp16 buffers (uint2 = 4 half voxels)
__device__ uint2 g_yp16[NV4];
__device__ uint2 g_tru16[NV4];
__device__ uint2 g_imgA16[NV4];
__device__ uint2 g_imgB16[NV4];
__device__ uint2 g_skel16[NV4];
__device__ float g_yp[NVOX];      // fp32 sigmoid (for tsens sum)
__device__ float g_acc[8];

__device__ __forceinline__ __half2 u2h(unsigned u) { return *reinterpret_cast<__half2*>(&u); }
__device__ __forceinline__ unsigned h2u(__half2 h) { return *reinterpret_cast<unsigned*>(&h); }

__device__ __forceinline__ uint2 hmin2u(uint2 a, uint2 b) {
    return make_uint2(h2u(__hmin2(u2h(a.x), u2h(b.x))), h2u(__hmin2(u2h(a.y), u2h(b.y))));
}
__device__ __forceinline__ uint2 hmax2u(uint2 a, uint2 b) {
    return make_uint2(h2u(__hmax2(u2h(a.x), u2h(b.x))), h2u(__hmax2(u2h(a.y), u2h(b.y))));
}
__device__ __forceinline__ uint2 hmin3u(uint2 a, uint2 b, uint2 c) { return hmin2u(hmin2u(a,b),c); }
__device__ __forceinline__ uint2 hmax3u(uint2 a, uint2 b, uint2 c) { return hmax2u(hmax2u(a,b),c); }

// x-window min/max over [x-1,x+1] for 4 packed halfs; clamp at volume edge
__device__ __forceinline__ uint2 hminS(uint2 v, int tx) {
    unsigned lb = __shfl_up_sync(FULLM, v.y, 1);
    unsigned rn = __shfl_down_sync(FULLM, v.x, 1);
    if (tx == 0)  lb = v.x << 16;
    if (tx == 31) rn = v.y >> 16;
    unsigned Lb = __byte_perm(v.x, v.y, 0x5432);
    unsigned La = __byte_perm(lb, v.x, 0x5432);
    unsigned Rb = __byte_perm(v.y, rn, 0x5432);
    uint2 L = make_uint2(La, Lb), R = make_uint2(Lb, Rb);
    return hmin3u(L, v, R);
}
__device__ __forceinline__ uint2 hmaxS(uint2 v, int tx) {
    unsigned lb = __shfl_up_sync(FULLM, v.y, 1);
    unsigned rn = __shfl_down_sync(FULLM, v.x, 1);
    if (tx == 0)  lb = v.x << 16;
    if (tx == 31) rn = v.y >> 16;
    unsigned Lb = __byte_perm(v.x, v.y, 0x5432);
    unsigned La = __byte_perm(lb, v.x, 0x5432);
    unsigned Rb = __byte_perm(v.y, rn, 0x5432);
    uint2 L = make_uint2(La, Lb), R = make_uint2(Lb, Rb);
    return hmax3u(L, v, R);
}

// relu(a - b) in packed half2, per word
__device__ __forceinline__ unsigned hrelusub(unsigned a, unsigned b) {
    return h2u(__hmax2(__hsub2(u2h(a), u2h(b)), u2h(0u)));
}

__device__ __forceinline__ const uint2* pickH(int sel) {
    if (sel == 0) return g_imgA16;
    if (sel == 1) return g_imgB16;
    if (sel == 2) return g_yp16;
    return g_tru16;
}
__device__ __forceinline__ const float* pickF(int sel, const float* ext) {
    return (sel == 2) ? g_yp : ext;
}

__global__ void zero_acc_kernel() {
    if (threadIdx.x < 8) g_acc[threadIdx.x] = 0.f;
}

// ---------------------------------------------------------------------------
// prep: yp = sigmoid(pred) (fp32 + fp16), tru16 = fp16(tru); dice sums
// ---------------------------------------------------------------------------
__global__ __launch_bounds__(256) void prep_kernel(const float* __restrict__ pred,
                                                   const float* __restrict__ tru) {
    __shared__ float sm[3][8];
    const float4* p4 = (const float4*)pred;
    const float4* t4 = (const float4*)tru;
    float4* y4 = (float4*)g_yp;
    int base = blockIdx.x * 1024 + threadIdx.x;
    float st = 0.f, sp = 0.f, stp = 0.f;
#pragma unroll
    for (int k = 0; k < 4; k++) {
        int i = base + k * 256;
        float4 t = t4[i];
        float4 x = p4[i];
        float4 p;
        p.x = 1.f / (1.f + __expf(-x.x));
        p.y = 1.f / (1.f + __expf(-x.y));
        p.z = 1.f / (1.f + __expf(-x.z));
        p.w = 1.f / (1.f + __expf(-x.w));
        y4[i] = p;
        uint2 ph, th;
        ph.x = h2u(__halves2half2(__float2half_rn(p.x), __float2half_rn(p.y)));
        ph.y = h2u(__halves2half2(__float2half_rn(p.z), __float2half_rn(p.w)));
        th.x = h2u(__halves2half2(__float2half_rn(t.x), __float2half_rn(t.y)));
        th.y = h2u(__halves2half2(__float2half_rn(t.z), __float2half_rn(t.w)));
        g_yp16[i] = ph;
        g_tru16[i] = th;
        st  += (t.x + t.y) + (t.z + t.w);
        sp  += (p.x + p.y) + (p.z + p.w);
        stp += (t.x*p.x + t.y*p.y) + (t.z*p.z + t.w*p.w);
    }
#pragma unroll
    for (int o = 16; o > 0; o >>= 1) {
        st  += __shfl_xor_sync(FULLM, st,  o);
        sp  += __shfl_xor_sync(FULLM, sp,  o);
        stp += __shfl_xor_sync(FULLM, stp, o);
    }
    int w = threadIdx.x >> 5, lane = threadIdx.x & 31;
    if (lane == 0) { sm[0][w] = st; sm[1][w] = sp; sm[2][w] = stp; }
    __syncthreads();
    if (threadIdx.x == 0) {
        float a = 0.f, b = 0.f, c = 0.f;
#pragma unroll
        for (int i = 0; i < 8; i++) { a += sm[0][i]; b += sm[1][i]; c += sm[2][i]; }
        atomicAdd(&g_acc[0], a); atomicAdd(&g_acc[1], b); atomicAdd(&g_acc[2], c);
    }
}

// ---------------------------------------------------------------------------
// init: skel16 = relu(x - dilate(erode(x)))  AND  g_imgA16 = erode(x)   [fp16]
// ---------------------------------------------------------------------------
__global__ __launch_bounds__(1024) void init_kernel(int inSel) {
    __shared__ uint2 As[32][32];
    __shared__ uint2 Ms[32][32];
    const uint2* __restrict__ x = pickH(inSel);

    const int tx = threadIdx.x, ty = threadIdx.y;
    const int b   = blockIdx.z;
    const int oz0 = blockIdx.y * ZLEN;
    const int oz1 = min(oz0 + ZLEN, VOL);
    const int gy  = blockIdx.x * OTY - 3 + ty;
    const bool vrow = (gy >= 0 && gy < VOL);
    const bool wr   = vrow && ty >= 3 && ty < 29;
    const int ym = ty > 0 ? ty - 1 : 0, yp = ty < 31 ? ty + 1 : 31;
    const int rowOff4 = b * (VOL3/4) + (vrow ? gy : 0) * (VOL/4) + tx;

    const uint2 P2 = make_uint2(HPINF2, HPINF2);
    const uint2 N2 = make_uint2(HNINF2, HNINF2);

    uint2 a_m1 = P2, a_m2 = P2, bxy_m1 = P2;
    uint2 m_m1 = N2, m_m2 = N2;
    uint2 e1_m1 = P2;

    int z0 = oz0 - 2;
    uint2 cur = P2;
    if (vrow && (unsigned)z0 < (unsigned)VOL)
        cur = x[z0 * (VOL2/4) + rowOff4];
    As[ty][tx] = cur;
    __syncthreads();

    for (int z = z0; z <= oz1 + 1; ++z) {
        uint2 nxt = P2;
        if (vrow && (unsigned)(z + 1) < (unsigned)VOL)
            nxt = x[(z + 1) * (VOL2/4) + rowOff4];

        uint2 up = As[ym][tx], dn = As[yp][tx];
        uint2 bxy = hmin3u(hminS(cur, tx), up, dn);
        uint2 e1 = hmin3u(a_m2, cur, bxy_m1);
        uint2 e1d = e1;
        if (!vrow || (unsigned)(z - 1) >= (unsigned)VOL) e1d = N2;
        uint2 hm = hmaxS(e1d, tx);
        Ms[ty][tx] = hm;
        __syncthreads();
        As[ty][tx] = nxt;
        uint2 mxy = hmax3u(hm, Ms[ym][tx], Ms[yp][tx]);
        int zo = z - 2;
        if (wr && zo >= oz0 && zo < oz1) {
            uint2 openv = hmax3u(m_m2, m_m1, mxy);
            uint2 s;
            s.x = hrelusub(a_m2.x, openv.x);
            s.y = hrelusub(a_m2.y, openv.y);
            int gi = zo * (VOL2/4) + rowOff4;
            g_skel16[gi] = s;
            g_imgA16[gi] = e1_m1;
        }
        __syncthreads();
        a_m2 = a_m1; a_m1 = cur; bxy_m1 = bxy;
        m_m2 = m_m1; m_m1 = mxy;
        e1_m1 = e1;
        cur = nxt;
    }
}

// ---------------------------------------------------------------------------
// iter (fp16, 2-stage, 1 barrier/plane): e2 = erode(imgE_k); open = dilate(e2);
// skel16 half2 update; write e2 as imgE_{k+1}. Output zo=z-3.
// ---------------------------------------------------------------------------
__global__ __launch_bounds__(1024) void iter_kernel(
    int inSel, int outSel, int doSum, int otherSel,
    const float* __restrict__ extOther, int accBase)
{
    extern __shared__ uint2 smemU[];   // 8*1024 (As) + 2*1024 (Ms) = 80 KB
    const int AS0 = 0, MS0 = 8192;

    const uint2* __restrict__ imgIn = pickH(inSel);
    uint2* imgOut = (outSel == 0) ? g_imgA16 : g_imgB16;
    const float* __restrict__ other = pickF(otherSel, extOther);

    const int tx = threadIdx.x, ty = threadIdx.y;
    const int b   = blockIdx.z;
    const int oz0 = blockIdx.y * ZLEN;
    const int oz1 = min(oz0 + ZLEN, VOL);
    const int gy  = blockIdx.x * OTY - 3 + ty;
    const bool vrow = (gy >= 0 && gy < VOL);
    const bool wr   = vrow && ty >= 3 && ty < 29;
    const int ym = ty > 0 ? ty - 1 : 0, yp = ty < 31 ? ty + 1 : 31;
    const int rowOff4 = b * (VOL3/4) + (vrow ? gy : 0) * (VOL/4) + tx;
    const int sIdx = ty * 32 + tx;

    const uint2 P2 = make_uint2(HPINF2, HPINF2);
    const uint2 N2 = make_uint2(HNINF2, HNINF2);

    uint2 bxy_m1 = P2;
    uint2 e2_m1 = P2, e2_m2 = P2;
    uint2 hm_m1 = N2;
    uint2 m_m1 = N2, m_m2 = N2;
    float sumS = 0.f, sumC = 0.f;

    const int z0 = oz0 - 2;
    uint2 cur = P2, nxtHold = P2;
    if (vrow && (unsigned)z0 < (unsigned)VOL)
        cur = imgIn[z0 * (VOL2/4) + rowOff4];
    if (vrow && (unsigned)(z0 + 1) < (unsigned)VOL)
        nxtHold = imgIn[(z0 + 1) * (VOL2/4) + rowOff4];

    smemU[AS0 + ((z0 + 8) & 7) * 1024 + sIdx] = cur;
    smemU[MS0 + sIdx]        = N2;
    smemU[MS0 + 1024 + sIdx] = N2;
    __syncthreads();

#pragma unroll 2
    for (int z = z0; z <= oz1 + 2; ++z) {
        const int aW  = AS0 + ((z + 9) & 7) * 1024;
        const int aC  = AS0 + ((z + 8) & 7) * 1024;
        const int aM2 = AS0 + ((z + 6) & 7) * 1024;
        const int aM3 = AS0 + ((z + 5) & 7) * 1024;
        const int mW  = MS0 + ((z + 7) & 1) * 1024;
        const int mR  = MS0 + ((z + 6) & 1) * 1024;

        const int zo = z - 3;
        const bool doOut = wr && zo >= oz0 && zo < oz1;
        const int gi = zo * (VOL2/4) + rowOff4;

        uint2 nxt2 = P2;
        if (vrow && (unsigned)(z + 2) < (unsigned)VOL)
            nxt2 = imgIn[(z + 2) * (VOL2/4) + rowOff4];
        uint2 sPre = make_uint2(0u, 0u);
        if (doOut) sPre = g_skel16[gi];

        smemU[aW + sIdx] = nxtHold;

        // stage 1: erosion e2(z-1)
        uint2 up = smemU[aC + ym * 32 + tx], dn = smemU[aC + yp * 32 + tx];
        uint2 bxy = hmin3u(hminS(cur, tx), up, dn);
        uint2 am2 = smemU[aM2 + sIdx];
        uint2 e2 = hmin3u(am2, cur, bxy_m1);
        uint2 e2d = e2;
        if (!vrow || (unsigned)(z - 1) >= (unsigned)VOL) e2d = N2;
        uint2 hm = hmaxS(e2d, tx);
        smemU[mW + sIdx] = hm;

        // stage 2: 3x3 in-plane max at z-2
        uint2 mxy = hmax3u(hm_m1, smemU[mR + ym * 32 + tx], smemU[mR + yp * 32 + tx]);

        // output at zo = z-3
        if (doOut) {
            uint2 imgE = smemU[aM3 + sIdx];
            uint2 openv = hmax3u(m_m2, m_m1, mxy);
            __half2 z2 = u2h(0u);
            __half2 d0 = __hmax2(__hsub2(u2h(imgE.x), u2h(openv.x)), z2);
            __half2 d1 = __hmax2(__hsub2(u2h(imgE.y), u2h(openv.y)), z2);
            __half2 s0 = u2h(sPre.x), s1 = u2h(sPre.y);
            __half2 i0 = __hmax2(__hfma2(__hneg2(s0), d0, d0), z2);
            __half2 i1 = __hmax2(__hfma2(__hneg2(s1), d1, d1), z2);
            s0 = __hadd2(s0, i0);
            s1 = __hadd2(s1, i1);
            if (!doSum) {
                g_skel16[gi] = make_uint2(h2u(s0), h2u(s1));
                imgOut[gi] = e2_m2;
            } else {
                float2 f0 = __half22float2(s0), f1 = __half22float2(s1);
                float4 o = ((const float4*)other)[gi];
                sumS += (f0.x + f0.y) + (f1.x + f1.y);
                sumC += (f0.x*o.x + f0.y*o.y) + (f1.x*o.z + f1.y*o.w);
            }
        }

        __syncthreads();

        cur = nxtHold; nxtHold = nxt2;
        bxy_m1 = bxy;
        e2_m2 = e2_m1; e2_m1 = e2;
        hm_m1 = hm;
        m_m2 = m_m1; m_m1 = mxy;
    }

    if (doSum) {
#pragma unroll
        for (int o = 16; o > 0; o >>= 1) {
            sumS += __shfl_xor_sync(FULLM, sumS, o);
            sumC += __shfl_xor_sync(FULLM, sumC, o);
        }
        int w = sIdx >> 5, lane = sIdx & 31;
        float* red = (float*)smemU;
        if (lane == 0) { red[w] = sumS; red[32 + w] = sumC; }
        __syncthreads();
        if (w == 0) {
            float s = red[lane], c = red[32 + lane];
#pragma unroll
            for (int o = 16; o > 0; o >>= 1) {
                s += __shfl_xor_sync(FULLM, s, o);
                c += __shfl_xor_sync(FULLM, c, o);
            }
            if (lane == 0) {
                atomicAdd(&g_acc[accBase], s);
                atomicAdd(&g_acc[accBase + 1], c);
            }
        }
    }
}

__global__ void final_kernel(float* out) {
    float st = g_acc[0], sp = g_acc[1], stp = g_acc[2];
    float skp = g_acc[3], skpt = g_acc[4], skt = g_acc[5], sktp = g_acc[6];
    float dice = 1.f - (2.f * stp + 1.f) / (st + sp + 1.f);
    float tprec = (skpt + 1.f) / (skp + 1.f);
    float tsens = (sktp + 1.f) / (skt + 1.f);
    float cl = 1.f - 2.f * (tprec * tsens) / (tprec + tsens);
    out[0] = 0.7f * dice + 0.3f * cl;
}

#define ITER_SMEM (10 * 1024 * 8)   // 80 KB

extern "C" void kernel_launch(void* const* d_in, const int* in_sizes, int n_in,
                              void* d_out, int out_size) {
    const float* pred = (const float*)d_in[0];
    const float* tru  = (const float*)d_in[1];
    float* out = (float*)d_out;

    static int smem_set = 0;
    if (!smem_set) {
        cudaFuncSetAttribute(iter_kernel, cudaFuncAttributeMaxDynamicSharedMemorySize, ITER_SMEM);
        smem_set = 1;
    }

    dim3 blk(32, 32);
    dim3 grd(NTY, ZSEG, NB);

    zero_acc_kernel<<<1, 32>>>();
    prep_kernel<<<NVOX / 4096, 256>>>(pred, tru);

    // ---- pred skeleton ----
    init_kernel<<<grd, blk>>>(2);
    for (int k = 1; k <= 16; ++k) {
        int inSel  = (k & 1) ? 0 : 1;
        int outSel = (k & 1) ? 1 : 0;
        int doSum  = (k == 16) ? 1 : 0;
        iter_kernel<<<grd, blk, ITER_SMEM>>>(inSel, outSel, doSum, 3, tru, 3);
    }

    // ---- true skeleton ----
    init_kernel<<<grd, blk>>>(3);
    for (int k = 1; k <= 16; ++k) {
        int inSel  = (k & 1) ? 0 : 1;
        int outSel = (k & 1) ? 1 : 0;
        int doSum  = (k == 16) ? 1 : 0;
        iter_kernel<<<grd, blk, ITER_SMEM>>>(inSel, outSel, doSum, 2, nullptr, 5);
    }

    final_kernel<<<1, 1>>>(out);
}